// round 1
// baseline (speedup 1.0000x reference)
#include <cuda_runtime.h>
#include <math.h>

#define NEXP    8
#define HDIM    4096
#define TOK     8
#define WARPS   8
#define THREADS 256
#define NTOK    16384            // 4 * 4096 tokens
#define NGROUP  (NTOK / TOK)     // 2048 warp-groups
#define H4      (HDIM / 4)       // 1024 float4 per row

__global__ __launch_bounds__(THREADS, 1)
void moe_router_kernel(const float* __restrict__ hs,
                       const float* __restrict__ rw,
                       float* __restrict__ out)
{
    extern __shared__ float sw[];          // [NEXP][HDIM] = 128 KB
    float4* sw4 = reinterpret_cast<float4*>(sw);

    // Stage router weights into shared memory (coalesced, once per block)
    {
        const float4* rw4 = reinterpret_cast<const float4*>(rw);
        #pragma unroll
        for (int i = threadIdx.x; i < NEXP * H4; i += THREADS)
            sw4[i] = rw4[i];
    }
    __syncthreads();

    const int lane = threadIdx.x & 31;
    const int wid  = threadIdx.x >> 5;
    const int gwarp = blockIdx.x * WARPS + wid;
    const int nwarp = gridDim.x * WARPS;

    float* out_w = out;                     // [NTOK, 2] top-k weights
    float* out_i = out + (size_t)NTOK * 2;  // [NTOK, 2] indices (as float)
    float* out_l = out + (size_t)NTOK * 4;  // [NTOK, 8] raw logits

    for (int g = gwarp; g < NGROUP; g += nwarp) {
        const size_t t0 = (size_t)g * TOK;
        const float4* hs4 = reinterpret_cast<const float4*>(hs) + t0 * H4;

        float acc[TOK][NEXP];
        #pragma unroll
        for (int t = 0; t < TOK; t++)
            #pragma unroll
            for (int e = 0; e < NEXP; e++)
                acc[t][e] = 0.0f;

        // K loop: each lane covers float4 slot (iter*32 + lane)
        for (int i = 0; i < H4 / 32; i++) {        // 32 iterations
            const int kk = i * 32 + lane;
            float4 w[NEXP];
            #pragma unroll
            for (int e = 0; e < NEXP; e++)
                w[e] = sw4[e * H4 + kk];

            #pragma unroll
            for (int t = 0; t < TOK; t++) {
                const float4 h = hs4[(size_t)t * H4 + kk];
                #pragma unroll
                for (int e = 0; e < NEXP; e++) {
                    acc[t][e] = fmaf(h.x, w[e].x, acc[t][e]);
                    acc[t][e] = fmaf(h.y, w[e].y, acc[t][e]);
                    acc[t][e] = fmaf(h.z, w[e].z, acc[t][e]);
                    acc[t][e] = fmaf(h.w, w[e].w, acc[t][e]);
                }
            }
        }

        // Butterfly reduction: every lane ends with all 64 sums
        #pragma unroll
        for (int off = 16; off > 0; off >>= 1) {
            #pragma unroll
            for (int t = 0; t < TOK; t++)
                #pragma unroll
                for (int e = 0; e < NEXP; e++)
                    acc[t][e] += __shfl_xor_sync(0xffffffffu, acc[t][e], off);
        }

        // Lanes 0..7: one token each — softmax + top-2 + renorm + writes
        if (lane < TOK) {
            float l[NEXP];
            #pragma unroll
            for (int t = 0; t < TOK; t++) {
                if (lane == t) {
                    #pragma unroll
                    for (int e = 0; e < NEXP; e++) l[e] = acc[t][e];
                }
            }

            const size_t tok = t0 + lane;

            // argmax (ties -> lowest index, matching jax.lax.top_k)
            int   i1 = 0; float v1 = l[0];
            #pragma unroll
            for (int e = 1; e < NEXP; e++)
                if (l[e] > v1) { v1 = l[e]; i1 = e; }
            int   i2 = -1; float v2 = -INFINITY;
            #pragma unroll
            for (int e = 0; e < NEXP; e++)
                if (e != i1 && l[e] > v2) { v2 = l[e]; i2 = e; }

            // renormalized top-2 softmax weights:
            // w_k = exp(l_k - m) / (exp(l_1 - m) + exp(l_2 - m))
            const float m  = v1;
            const float e1 = 1.0f;                // expf(v1 - m)
            const float e2 = __expf(v2 - m);
            const float r  = 1.0f / (e1 + e2);

            out_w[tok * 2 + 0] = e1 * r;
            out_w[tok * 2 + 1] = e2 * r;
            out_i[tok * 2 + 0] = (float)i1;
            out_i[tok * 2 + 1] = (float)i2;
            #pragma unroll
            for (int e = 0; e < NEXP; e++)
                out_l[tok * NEXP + e] = l[e];
        }
    }
}

extern "C" void kernel_launch(void* const* d_in, const int* in_sizes, int n_in,
                              void* d_out, int out_size)
{
    const float* hs = (const float*)d_in[0];   // hidden_states [4,4096,4096] f32
    const float* rw = (const float*)d_in[1];   // router_weight [8,4096] f32
    float* out = (float*)d_out;

    (void)in_sizes; (void)n_in; (void)out_size;

    cudaFuncSetAttribute(moe_router_kernel,
                         cudaFuncAttributeMaxDynamicSharedMemorySize,
                         NEXP * HDIM * (int)sizeof(float));

    moe_router_kernel<<<152, THREADS, NEXP * HDIM * sizeof(float)>>>(hs, rw, out);
}

// round 2
// speedup vs baseline: 1.3670x; 1.3670x over previous
#include <cuda_runtime.h>
#include <math.h>

#define NEXP    8
#define HDIM    4096
#define TOK     4
#define WARPS   16
#define THREADS 512
#define NTOK    16384            // 4 * 4096 tokens
#define NGROUP  (NTOK / TOK)     // 4096 warp-groups
#define H4      (HDIM / 4)       // 1024 float4 per row
#define KITERS  (H4 / 32)        // 32 k-iterations per group

__global__ __launch_bounds__(THREADS, 1)
void moe_router_kernel(const float* __restrict__ hs,
                       const float* __restrict__ rw,
                       float* __restrict__ out)
{
    extern __shared__ float sw[];          // [NEXP][HDIM] = 128 KB
    float4* sw4 = reinterpret_cast<float4*>(sw);

    // Stage router weights into shared memory (coalesced, once per block)
    {
        const float4* rw4 = reinterpret_cast<const float4*>(rw);
        #pragma unroll
        for (int i = threadIdx.x; i < NEXP * H4; i += THREADS)
            sw4[i] = rw4[i];
    }
    __syncthreads();

    const int lane  = threadIdx.x & 31;
    const int wid   = threadIdx.x >> 5;
    const int gwarp = blockIdx.x * WARPS + wid;
    const int nwarp = gridDim.x * WARPS;

    float* out_w = out;                     // [NTOK, 2] top-k weights
    float* out_i = out + (size_t)NTOK * 2;  // [NTOK, 2] indices (as float)
    float* out_l = out + (size_t)NTOK * 4;  // [NTOK, 8] raw logits

    for (int g = gwarp; g < NGROUP; g += nwarp) {
        const size_t t0 = (size_t)g * TOK;
        const float4* hs4 = reinterpret_cast<const float4*>(hs) + t0 * H4;

        float acc[TOK][NEXP];
        #pragma unroll
        for (int t = 0; t < TOK; t++)
            #pragma unroll
            for (int e = 0; e < NEXP; e++)
                acc[t][e] = 0.0f;

        // Double-buffered hidden loads: iteration i consumes hbuf[i&1],
        // prefetches hbuf[(i+1)&1] before the FMA chain.
        float4 hbuf[2][TOK];
        #pragma unroll
        for (int t = 0; t < TOK; t++)
            hbuf[0][t] = __ldcs(&hs4[(size_t)t * H4 + lane]);

        #pragma unroll 4
        for (int i = 0; i < KITERS; i++) {
            const int cur = i & 1;
            const int kk  = i * 32 + lane;

            if (i + 1 < KITERS) {
                const int kk2 = kk + 32;
                #pragma unroll
                for (int t = 0; t < TOK; t++)
                    hbuf[cur ^ 1][t] = __ldcs(&hs4[(size_t)t * H4 + kk2]);
            }

            float4 w[NEXP];
            #pragma unroll
            for (int e = 0; e < NEXP; e++)
                w[e] = sw4[e * H4 + kk];

            #pragma unroll
            for (int t = 0; t < TOK; t++) {
                const float4 h = hbuf[cur][t];
                #pragma unroll
                for (int e = 0; e < NEXP; e++) {
                    acc[t][e] = fmaf(h.x, w[e].x, acc[t][e]);
                    acc[t][e] = fmaf(h.y, w[e].y, acc[t][e]);
                    acc[t][e] = fmaf(h.z, w[e].z, acc[t][e]);
                    acc[t][e] = fmaf(h.w, w[e].w, acc[t][e]);
                }
            }
        }

        // Butterfly reduction: every lane ends with all TOK*NEXP sums
        #pragma unroll
        for (int off = 16; off > 0; off >>= 1) {
            #pragma unroll
            for (int t = 0; t < TOK; t++)
                #pragma unroll
                for (int e = 0; e < NEXP; e++)
                    acc[t][e] += __shfl_xor_sync(0xffffffffu, acc[t][e], off);
        }

        // Lanes 0..TOK-1: one token each — top-2 + renorm + writes
        if (lane < TOK) {
            float l[NEXP];
            #pragma unroll
            for (int t = 0; t < TOK; t++) {
                if (lane == t) {
                    #pragma unroll
                    for (int e = 0; e < NEXP; e++) l[e] = acc[t][e];
                }
            }

            const size_t tok = t0 + lane;

            // argmax (ties -> lowest index, matching jax.lax.top_k)
            int   i1 = 0; float v1 = l[0];
            #pragma unroll
            for (int e = 1; e < NEXP; e++)
                if (l[e] > v1) { v1 = l[e]; i1 = e; }
            int   i2 = -1; float v2 = -INFINITY;
            #pragma unroll
            for (int e = 0; e < NEXP; e++)
                if (e != i1 && l[e] > v2) { v2 = l[e]; i2 = e; }

            // renormalized top-2 softmax weights
            const float e2 = __expf(v2 - v1);
            const float r  = 1.0f / (1.0f + e2);

            out_w[tok * 2 + 0] = r;
            out_w[tok * 2 + 1] = e2 * r;
            out_i[tok * 2 + 0] = (float)i1;
            out_i[tok * 2 + 1] = (float)i2;
            #pragma unroll
            for (int e = 0; e < NEXP; e++)
                out_l[tok * NEXP + e] = l[e];
        }
    }
}

extern "C" void kernel_launch(void* const* d_in, const int* in_sizes, int n_in,
                              void* d_out, int out_size)
{
    const float* hs = (const float*)d_in[0];   // hidden_states [4,4096,4096] f32
    const float* rw = (const float*)d_in[1];   // router_weight [8,4096] f32
    float* out = (float*)d_out;

    (void)in_sizes; (void)n_in; (void)out_size;

    cudaFuncSetAttribute(moe_router_kernel,
                         cudaFuncAttributeMaxDynamicSharedMemorySize,
                         NEXP * HDIM * (int)sizeof(float));

    moe_router_kernel<<<152, THREADS, NEXP * HDIM * sizeof(float)>>>(hs, rw, out);
}